// round 12
// baseline (speedup 1.0000x reference)
#include <cuda_runtime.h>

// LCC over [B=2,1,192,192,192] fp32, fully fused z-sweep.
// Round-12: the ACTUAL round-3 kernel (parity double-buffered smem,
// 2 barriers/plane, 94.7us) with 192-thread CTAs (32x6, COVY=12, TOUTY=8):
// 80 regs x 192thr x 4 = 61440 < 64K -> 4 independent barrier groups/SM.
// (Round-11 accidentally tested a 4-barrier/plane variant; this is the
// clean 2-barrier x 4-group combination.)

namespace {
constexpr int NV   = 192;
constexpr int NV2  = NV * NV;
constexpr long long NV3 = (long long)NV * NV2;
constexpr int BYT  = 6;
constexpr int RY   = 2;
constexpr int COVY = BYT * RY;      // 12 covered rows
constexpr int TOUTX = 48;           // outputs/block in x (lanes cover 64)
constexpr int TOUTY = COVY - 4;     // 8
constexpr int ZCHUNKS = 8;
constexpr int ZC   = NV / ZCHUNKS;  // 24 (divisible by 3)
constexpr float EPSV  = 1e-5f;
constexpr float INV27 = 1.0f / 27.0f;
constexpr unsigned FULL = 0xffffffffu;
}

__device__ __forceinline__ float2 a2(float2 a, float2 b) {
    float2 r;
    asm("{.reg .b64 ra,rb,rc;\n\t"
        "mov.b64 ra,{%2,%3};\n\t"
        "mov.b64 rb,{%4,%5};\n\t"
        "add.rn.f32x2 rc,ra,rb;\n\t"
        "mov.b64 {%0,%1},rc;}\n\t"
        : "=f"(r.x), "=f"(r.y)
        : "f"(a.x), "f"(a.y), "f"(b.x), "f"(b.y));
    return r;
}
__device__ __forceinline__ float2 m2(float2 a, float2 b) {
    float2 r;
    asm("{.reg .b64 ra,rb,rc;\n\t"
        "mov.b64 ra,{%2,%3};\n\t"
        "mov.b64 rb,{%4,%5};\n\t"
        "mul.rn.f32x2 rc,ra,rb;\n\t"
        "mov.b64 {%0,%1},rc;}\n\t"
        : "=f"(r.x), "=f"(r.y)
        : "f"(a.x), "f"(a.y), "f"(b.x), "f"(b.y));
    return r;
}
__device__ __forceinline__ float2 f2ma(float2 a, float2 b, float2 c) {
    float2 r;
    asm("{.reg .b64 ra,rb,rc,rd;\n\t"
        "mov.b64 ra,{%2,%3};\n\t"
        "mov.b64 rb,{%4,%5};\n\t"
        "mov.b64 rc,{%6,%7};\n\t"
        "fma.rn.f32x2 rd,ra,rb,rc;\n\t"
        "mov.b64 {%0,%1},rd;}\n\t"
        : "=f"(r.x), "=f"(r.y)
        : "f"(a.x), "f"(a.y), "f"(b.x), "f"(b.y), "f"(c.x), "f"(c.y));
    return r;
}

__global__ void zero_out_kernel(float* out, int n) {
    int i = blockIdx.x * blockDim.x + threadIdx.x;
    if (i < n) out[i] = 0.0f;
}

__global__ __launch_bounds__(32 * BYT, 4)
void lcc_kernel(const float* __restrict__ gF,
                const float* __restrict__ gM,
                float* __restrict__ out)
{
    __shared__ float2 sA [2][COVY][33];
    __shared__ float2 sB [2][COVY][33];
    __shared__ float2 sQ0[2][COVY][33];
    __shared__ float2 sQ1[2][COVY][33];
    __shared__ float2 sQ2[2][COVY][33];
    __shared__ float  wsum[BYT];

    const int tx  = threadIdx.x;
    const int ty  = threadIdx.y;
    const int yl0 = ty * RY;
    const int b   = blockIdx.z / ZCHUNKS;
    const int Z0  = (blockIdx.z % ZCHUNKS) * ZC;

    const int x_nom0 = (int)blockIdx.x * TOUTX - 2 + 2 * tx;   // even
    const int xbase  = min(max(x_nom0, 0), NV - 2);
    const bool fixlo  = (x_nom0 < 0);
    const bool fixhi  = (x_nom0 > NV - 2);
    const bool fixXlo = (x_nom0 == 0);
    const bool fixXhi = (x_nom0 + 1 == NV - 1);

    const int y_nom0 = (int)blockIdx.y * TOUTY - 2 + yl0;
    const bool fixYup = (y_nom0 == 0);
    const bool fixYdn = (y_nom0 + 1 == NV - 1);

    int yoff[RY];
#pragma unroll
    for (int i = 0; i < RY; i++)
        yoff[i] = min(max(y_nom0 + i, 0), NV - 1) * NV + xbase;

    const float* F = gF + (long long)b * NV3;
    const float* M = gM + (long long)b * NV3;

    float2 rF[3][RY], rM[3][RY];               // raw plane ring
    float2 pA[3][RY], pB[3][RY], pC[3][RY];    // P plane ring (FM, FF, MM)
    float2 acc = make_float2(0.f, 0.f);
    int sp = 0, bp = 0;

    const float2 NEGI = make_float2(-INV27, -INV27);
    const float2 EPS2 = make_float2(EPSV, EPSV);

    const bool okl = (tx >= 1 && tx <= 24);
    float2 maskp[RY];
#pragma unroll
    for (int i = 0; i < RY; i++) {
        int yloc = yl0 + i;
        float m = (okl && yloc >= 2 && yloc < 2 + TOUTY) ? 1.0f : 0.0f;
        maskp[i] = make_float2(m, m);
    }

    auto loadp = [&](int z, float2 (&oF)[RY], float2 (&oM)[RY]) {
        z = min(max(z, 0), NV - 1);
        const float* fp = F + z * NV2;
        const float* mp = M + z * NV2;
#pragma unroll
        for (int i = 0; i < RY; i++) {
            float2 vF = __ldg(reinterpret_cast<const float2*>(fp + yoff[i]));
            float2 vM = __ldg(reinterpret_cast<const float2*>(mp + yoff[i]));
            oF[i].x = fixhi ? vF.y : vF.x;  oF[i].y = fixlo ? vF.x : vF.y;
            oM[i].x = fixhi ? vM.y : vM.x;  oM[i].y = fixlo ? vM.x : vM.y;
        }
    };

    const int rup = yl0 ? yl0 - 1 : 0;
    const int rdn = (yl0 + RY < COVY) ? yl0 + RY : COVY - 1;

    // P for the plane in raw slot ic (ip,ic,in_ = planes j-1, j, j+1); -> slot iw.
    auto stepP = [&](int ip, int ic, int in_, int iw) {
        float2 zf[RY], zm[RY];
#pragma unroll
        for (int i = 0; i < RY; i++) {
            zf[i] = a2(a2(rF[ip][i], rF[ic][i]), rF[in_][i]);
            zm[i] = a2(a2(rM[ip][i], rM[ic][i]), rM[in_][i]);
            sA[sp][yl0 + i][tx] = zf[i];
            sB[sp][yl0 + i][tx] = zm[i];
        }
        __syncthreads();
        float2 upF = sA[sp][rup][tx], dnF = sA[sp][rdn][tx];
        float2 upM = sB[sp][rup][tx], dnM = sB[sp][rdn][tx];
        float2 yf[RY], ym[RY];
        yf[0] = a2(a2(upF, zf[0]), zf[1]);  yf[1] = a2(a2(zf[0], zf[1]), dnF);
        ym[0] = a2(a2(upM, zm[0]), zm[1]);  ym[1] = a2(a2(zm[0], zm[1]), dnM);
#pragma unroll
        for (int i = 0; i < RY; i++) {
            float lF = __shfl_up_sync(FULL, yf[i].y, 1);
            float rG = __shfl_down_sync(FULL, yf[i].x, 1);
            float pF = yf[i].x + yf[i].y;
            float2 sF = make_float2(lF + pF, pF + rG);
            float lM = __shfl_up_sync(FULL, ym[i].y, 1);
            float rH = __shfl_down_sync(FULL, ym[i].x, 1);
            float pM = ym[i].x + ym[i].y;
            float2 sM = make_float2(lM + pM, pM + rH);
            float2 dF = f2ma(sF, NEGI, rF[ic][i]);
            float2 dM = f2ma(sM, NEGI, rM[ic][i]);
            pA[iw][i] = m2(dF, dM);
            pB[iw][i] = m2(dF, dF);
            pC[iw][i] = m2(dM, dM);
        }
        sp ^= 1;
    };

    // second box over P slots (i0,i1,i2) = P(j-1),P(j),P(j+1); score plane j.
    auto box2 = [&](int i0, int i1, int i2) {
        float2 zA[RY], zB[RY], zD[RY];
#pragma unroll
        for (int i = 0; i < RY; i++) {
            zA[i] = a2(a2(pA[i0][i], pA[i1][i]), pA[i2][i]);
            zB[i] = a2(a2(pB[i0][i], pB[i1][i]), pB[i2][i]);
            zD[i] = a2(a2(pC[i0][i], pC[i1][i]), pC[i2][i]);
            sQ0[bp][yl0 + i][tx] = zA[i];
            sQ1[bp][yl0 + i][tx] = zB[i];
            sQ2[bp][yl0 + i][tx] = zD[i];
        }
        __syncthreads();
        float2 uA = sQ0[bp][rup][tx], dA = sQ0[bp][rdn][tx];
        float2 uB = sQ1[bp][rup][tx], dB = sQ1[bp][rdn][tx];
        float2 uD = sQ2[bp][rup][tx], dD = sQ2[bp][rdn][tx];
        uA = fixYup ? zA[0] : uA;  dA = fixYdn ? zA[1] : dA;
        uB = fixYup ? zB[0] : uB;  dB = fixYdn ? zB[1] : dB;
        uD = fixYup ? zD[0] : uD;  dD = fixYdn ? zD[1] : dD;
        float2 ybA[RY], ybB[RY], ybD[RY];
        ybA[0] = a2(a2(uA, zA[0]), zA[1]);  ybA[1] = a2(a2(zA[0], zA[1]), dA);
        ybB[0] = a2(a2(uB, zB[0]), zB[1]);  ybB[1] = a2(a2(zB[0], zB[1]), dB);
        ybD[0] = a2(a2(uD, zD[0]), zD[1]);  ybD[1] = a2(a2(zD[0], zD[1]), dD);
#pragma unroll
        for (int i = 0; i < RY; i++) {
            float lA = __shfl_up_sync(FULL, ybA[i].y, 1);
            float rA = __shfl_down_sync(FULL, ybA[i].x, 1);
            float pA_ = ybA[i].x + ybA[i].y;
            float2 crA = make_float2((fixXlo ? ybA[i].x : lA) + pA_,
                                     pA_ + (fixXhi ? ybA[i].y : rA));
            float lB = __shfl_up_sync(FULL, ybB[i].y, 1);
            float rB = __shfl_down_sync(FULL, ybB[i].x, 1);
            float pB_ = ybB[i].x + ybB[i].y;
            float2 crB = make_float2((fixXlo ? ybB[i].x : lB) + pB_,
                                     pB_ + (fixXhi ? ybB[i].y : rB));
            float lD = __shfl_up_sync(FULL, ybD[i].y, 1);
            float rD = __shfl_down_sync(FULL, ybD[i].x, 1);
            float pD_ = ybD[i].x + ybD[i].y;
            float2 crD = make_float2((fixXlo ? ybD[i].x : lD) + pD_,
                                     pD_ + (fixXhi ? ybD[i].y : rD));
            float2 num = m2(crA, crA);
            float2 den = f2ma(crB, crD, EPS2);
            float2 zv  = make_float2(__fdividef(num.x, den.x),
                                     __fdividef(num.y, den.y));
            acc = f2ma(zv, maskp[i], acc);
        }
        bp ^= 1;
    };

    // ---- Prologue: P(Z0-1),P(Z0),P(Z0+1) in P[0..2]; raw[0]=Z0+1, raw[1]=Z0+2 ----
    if (Z0 == 0) {
        loadp(0, rF[2], rM[2]);
        loadp(1, rF[0], rM[0]);
#pragma unroll
        for (int i = 0; i < RY; i++) { rF[1][i] = rF[2][i]; rM[1][i] = rM[2][i]; }
        stepP(1, 2, 0, 1);   // P(0) -> P[1]
#pragma unroll
        for (int i = 0; i < RY; i++) {   // P(-1) := P(0)
            pA[0][i] = pA[1][i]; pB[0][i] = pB[1][i]; pC[0][i] = pC[1][i];
        }
        loadp(2, rF[1], rM[1]);
        stepP(2, 0, 1, 2);   // P(1) -> P[2]
    } else {
        loadp(Z0 - 2, rF[0], rM[0]);
        loadp(Z0 - 1, rF[1], rM[1]);
        loadp(Z0,     rF[2], rM[2]);
        stepP(0, 1, 2, 0);   // P(Z0-1)
        loadp(Z0 + 1, rF[0], rM[0]);
        stepP(1, 2, 0, 1);   // P(Z0)
        loadp(Z0 + 2, rF[1], rM[1]);
        stepP(2, 0, 1, 2);   // P(Z0+1)
    }

    // ---- Main z sweep, unrolled by 3 with static ring rotation ----
    auto body = [&](int j, int s0, int s1, int s2) {
        loadp(j + 3, rF[s2], rM[s2]);   // overwrite oldest raw slot (clamped)
        box2(s0, s1, s2);               // output plane j
        if (j != Z0 + ZC - 1) {
            if (j + 2 < NV) {
                stepP(s0, s1, s2, s0);  // P(j+2) -> oldest P slot
            } else {
#pragma unroll
                for (int i = 0; i < RY; i++) {  // P(j+2) := P(NV-1)
                    pA[s0][i] = pA[s2][i];
                    pB[s0][i] = pB[s2][i];
                    pC[s0][i] = pC[s2][i];
                }
            }
        }
    };
    for (int kb = 0; kb < ZC; kb += 3) {
        body(Z0 + kb,     0, 1, 2);
        body(Z0 + kb + 1, 1, 2, 0);
        body(Z0 + kb + 2, 2, 0, 1);
    }

    // ---- Reduction ----
    float t = acc.x + acc.y;
#pragma unroll
    for (int o = 16; o > 0; o >>= 1)
        t += __shfl_xor_sync(FULL, t, o);
    if (tx == 0) wsum[ty] = t;
    __syncthreads();
    if (tx == 0 && ty == 0) {
        float s = 0.0f;
#pragma unroll
        for (int i = 0; i < BYT; i++) s += wsum[i];
        atomicAdd(&out[b], s * (-1.0f / (float)NV3));
    }
}

extern "C" void kernel_launch(void* const* d_in, const int* in_sizes, int n_in,
                              void* d_out, int out_size) {
    const float* F = (const float*)d_in[0];
    const float* M = (const float*)d_in[1];
    float* out = (float*)d_out;

    const int B = (int)(in_sizes[0] / (long long)NV3);

    zero_out_kernel<<<1, 32>>>(out, out_size);

    dim3 block(32, BYT, 1);
    dim3 grid(NV / TOUTX, NV / TOUTY, B * ZCHUNKS);
    lcc_kernel<<<grid, block>>>(F, M, out);
}

// round 13
// speedup vs baseline: 1.0978x; 1.0978x over previous
#include <cuda_runtime.h>

// LCC over [B=2,1,192,192,192] fp32, fully fused z-sweep.
// Round-13: the round-3 kernel (94.7us; parity double-buffered smem,
// 2 barriers/plane, 32x8 float2 lanes) re-tiled to a SINGLE WAVE:
// ZCHUNKS=3 -> ZC=64 planes/CTA -> 384 CTAs <= 444 resident slots
// (148 SMs x 3 CTAs). Eliminates R3's 31%-full third wave.
// ZC=64 = 21*3 + 1: unroll-by-3 loop + one remainder body call.

namespace {
constexpr int NV   = 192;
constexpr int NV2  = NV * NV;
constexpr long long NV3 = (long long)NV * NV2;
constexpr int BYT  = 8;
constexpr int RY   = 2;
constexpr int COVY = BYT * RY;      // 16 covered rows
constexpr int TOUTX = 48;           // outputs/block in x (lanes cover 64)
constexpr int TOUTY = COVY - 4;     // 12
constexpr int ZCHUNKS = 3;
constexpr int ZC   = NV / ZCHUNKS;  // 64 planes per CTA
constexpr float EPSV  = 1e-5f;
constexpr float INV27 = 1.0f / 27.0f;
constexpr unsigned FULL = 0xffffffffu;
}

__device__ __forceinline__ float2 a2(float2 a, float2 b) {
    float2 r;
    asm("{.reg .b64 ra,rb,rc;\n\t"
        "mov.b64 ra,{%2,%3};\n\t"
        "mov.b64 rb,{%4,%5};\n\t"
        "add.rn.f32x2 rc,ra,rb;\n\t"
        "mov.b64 {%0,%1},rc;}\n\t"
        : "=f"(r.x), "=f"(r.y)
        : "f"(a.x), "f"(a.y), "f"(b.x), "f"(b.y));
    return r;
}
__device__ __forceinline__ float2 m2(float2 a, float2 b) {
    float2 r;
    asm("{.reg .b64 ra,rb,rc;\n\t"
        "mov.b64 ra,{%2,%3};\n\t"
        "mov.b64 rb,{%4,%5};\n\t"
        "mul.rn.f32x2 rc,ra,rb;\n\t"
        "mov.b64 {%0,%1},rc;}\n\t"
        : "=f"(r.x), "=f"(r.y)
        : "f"(a.x), "f"(a.y), "f"(b.x), "f"(b.y));
    return r;
}
__device__ __forceinline__ float2 f2ma(float2 a, float2 b, float2 c) {
    float2 r;
    asm("{.reg .b64 ra,rb,rc,rd;\n\t"
        "mov.b64 ra,{%2,%3};\n\t"
        "mov.b64 rb,{%4,%5};\n\t"
        "mov.b64 rc,{%6,%7};\n\t"
        "fma.rn.f32x2 rd,ra,rb,rc;\n\t"
        "mov.b64 {%0,%1},rd;}\n\t"
        : "=f"(r.x), "=f"(r.y)
        : "f"(a.x), "f"(a.y), "f"(b.x), "f"(b.y), "f"(c.x), "f"(c.y));
    return r;
}

__global__ void zero_out_kernel(float* out, int n) {
    int i = blockIdx.x * blockDim.x + threadIdx.x;
    if (i < n) out[i] = 0.0f;
}

__global__ __launch_bounds__(256, 3)
void lcc_kernel(const float* __restrict__ gF,
                const float* __restrict__ gM,
                float* __restrict__ out)
{
    __shared__ float2 sA [2][COVY][33];
    __shared__ float2 sB [2][COVY][33];
    __shared__ float2 sQ0[2][COVY][33];
    __shared__ float2 sQ1[2][COVY][33];
    __shared__ float2 sQ2[2][COVY][33];
    __shared__ float  wsum[BYT];

    const int tx  = threadIdx.x;
    const int ty  = threadIdx.y;
    const int yl0 = ty * RY;
    const int b   = blockIdx.z / ZCHUNKS;
    const int Z0  = (blockIdx.z % ZCHUNKS) * ZC;

    const int x_nom0 = (int)blockIdx.x * TOUTX - 2 + 2 * tx;   // even
    const int xbase  = min(max(x_nom0, 0), NV - 2);
    const bool fixlo  = (x_nom0 < 0);
    const bool fixhi  = (x_nom0 > NV - 2);
    const bool fixXlo = (x_nom0 == 0);
    const bool fixXhi = (x_nom0 + 1 == NV - 1);

    const int y_nom0 = (int)blockIdx.y * TOUTY - 2 + yl0;
    const bool fixYup = (y_nom0 == 0);
    const bool fixYdn = (y_nom0 + 1 == NV - 1);

    int yoff[RY];
#pragma unroll
    for (int i = 0; i < RY; i++)
        yoff[i] = min(max(y_nom0 + i, 0), NV - 1) * NV + xbase;

    const float* F = gF + (long long)b * NV3;
    const float* M = gM + (long long)b * NV3;

    float2 rF[3][RY], rM[3][RY];               // raw plane ring
    float2 pA[3][RY], pB[3][RY], pC[3][RY];    // P plane ring (FM, FF, MM)
    float2 acc = make_float2(0.f, 0.f);
    int sp = 0, bp = 0;

    const float2 NEGI = make_float2(-INV27, -INV27);
    const float2 EPS2 = make_float2(EPSV, EPSV);

    const bool okl = (tx >= 1 && tx <= 24);
    float2 maskp[RY];
#pragma unroll
    for (int i = 0; i < RY; i++) {
        int yloc = yl0 + i;
        float m = (okl && yloc >= 2 && yloc < 2 + TOUTY) ? 1.0f : 0.0f;
        maskp[i] = make_float2(m, m);
    }

    auto loadp = [&](int z, float2 (&oF)[RY], float2 (&oM)[RY]) {
        z = min(max(z, 0), NV - 1);
        const float* fp = F + z * NV2;
        const float* mp = M + z * NV2;
#pragma unroll
        for (int i = 0; i < RY; i++) {
            float2 vF = __ldg(reinterpret_cast<const float2*>(fp + yoff[i]));
            float2 vM = __ldg(reinterpret_cast<const float2*>(mp + yoff[i]));
            oF[i].x = fixhi ? vF.y : vF.x;  oF[i].y = fixlo ? vF.x : vF.y;
            oM[i].x = fixhi ? vM.y : vM.x;  oM[i].y = fixlo ? vM.x : vM.y;
        }
    };

    const int rup = yl0 ? yl0 - 1 : 0;
    const int rdn = (yl0 + RY < COVY) ? yl0 + RY : COVY - 1;

    // P for the plane in raw slot ic (ip,ic,in_ = planes j-1, j, j+1); -> slot iw.
    auto stepP = [&](int ip, int ic, int in_, int iw) {
        float2 zf[RY], zm[RY];
#pragma unroll
        for (int i = 0; i < RY; i++) {
            zf[i] = a2(a2(rF[ip][i], rF[ic][i]), rF[in_][i]);
            zm[i] = a2(a2(rM[ip][i], rM[ic][i]), rM[in_][i]);
            sA[sp][yl0 + i][tx] = zf[i];
            sB[sp][yl0 + i][tx] = zm[i];
        }
        __syncthreads();
        float2 upF = sA[sp][rup][tx], dnF = sA[sp][rdn][tx];
        float2 upM = sB[sp][rup][tx], dnM = sB[sp][rdn][tx];
        float2 yf[RY], ym[RY];
        yf[0] = a2(a2(upF, zf[0]), zf[1]);  yf[1] = a2(a2(zf[0], zf[1]), dnF);
        ym[0] = a2(a2(upM, zm[0]), zm[1]);  ym[1] = a2(a2(zm[0], zm[1]), dnM);
#pragma unroll
        for (int i = 0; i < RY; i++) {
            float lF = __shfl_up_sync(FULL, yf[i].y, 1);
            float rG = __shfl_down_sync(FULL, yf[i].x, 1);
            float pF = yf[i].x + yf[i].y;
            float2 sF = make_float2(lF + pF, pF + rG);
            float lM = __shfl_up_sync(FULL, ym[i].y, 1);
            float rH = __shfl_down_sync(FULL, ym[i].x, 1);
            float pM = ym[i].x + ym[i].y;
            float2 sM = make_float2(lM + pM, pM + rH);
            float2 dF = f2ma(sF, NEGI, rF[ic][i]);
            float2 dM = f2ma(sM, NEGI, rM[ic][i]);
            pA[iw][i] = m2(dF, dM);
            pB[iw][i] = m2(dF, dF);
            pC[iw][i] = m2(dM, dM);
        }
        sp ^= 1;
    };

    // second box over P slots (i0,i1,i2) = P(j-1),P(j),P(j+1); score plane j.
    auto box2 = [&](int i0, int i1, int i2) {
        float2 zA[RY], zB[RY], zD[RY];
#pragma unroll
        for (int i = 0; i < RY; i++) {
            zA[i] = a2(a2(pA[i0][i], pA[i1][i]), pA[i2][i]);
            zB[i] = a2(a2(pB[i0][i], pB[i1][i]), pB[i2][i]);
            zD[i] = a2(a2(pC[i0][i], pC[i1][i]), pC[i2][i]);
            sQ0[bp][yl0 + i][tx] = zA[i];
            sQ1[bp][yl0 + i][tx] = zB[i];
            sQ2[bp][yl0 + i][tx] = zD[i];
        }
        __syncthreads();
        float2 uA = sQ0[bp][rup][tx], dA = sQ0[bp][rdn][tx];
        float2 uB = sQ1[bp][rup][tx], dB = sQ1[bp][rdn][tx];
        float2 uD = sQ2[bp][rup][tx], dD = sQ2[bp][rdn][tx];
        uA = fixYup ? zA[0] : uA;  dA = fixYdn ? zA[1] : dA;
        uB = fixYup ? zB[0] : uB;  dB = fixYdn ? zB[1] : dB;
        uD = fixYup ? zD[0] : uD;  dD = fixYdn ? zD[1] : dD;
        float2 ybA[RY], ybB[RY], ybD[RY];
        ybA[0] = a2(a2(uA, zA[0]), zA[1]);  ybA[1] = a2(a2(zA[0], zA[1]), dA);
        ybB[0] = a2(a2(uB, zB[0]), zB[1]);  ybB[1] = a2(a2(zB[0], zB[1]), dB);
        ybD[0] = a2(a2(uD, zD[0]), zD[1]);  ybD[1] = a2(a2(zD[0], zD[1]), dD);
#pragma unroll
        for (int i = 0; i < RY; i++) {
            float lA = __shfl_up_sync(FULL, ybA[i].y, 1);
            float rA = __shfl_down_sync(FULL, ybA[i].x, 1);
            float pA_ = ybA[i].x + ybA[i].y;
            float2 crA = make_float2((fixXlo ? ybA[i].x : lA) + pA_,
                                     pA_ + (fixXhi ? ybA[i].y : rA));
            float lB = __shfl_up_sync(FULL, ybB[i].y, 1);
            float rB = __shfl_down_sync(FULL, ybB[i].x, 1);
            float pB_ = ybB[i].x + ybB[i].y;
            float2 crB = make_float2((fixXlo ? ybB[i].x : lB) + pB_,
                                     pB_ + (fixXhi ? ybB[i].y : rB));
            float lD = __shfl_up_sync(FULL, ybD[i].y, 1);
            float rD = __shfl_down_sync(FULL, ybD[i].x, 1);
            float pD_ = ybD[i].x + ybD[i].y;
            float2 crD = make_float2((fixXlo ? ybD[i].x : lD) + pD_,
                                     pD_ + (fixXhi ? ybD[i].y : rD));
            float2 num = m2(crA, crA);
            float2 den = f2ma(crB, crD, EPS2);
            float2 zv  = make_float2(__fdividef(num.x, den.x),
                                     __fdividef(num.y, den.y));
            acc = f2ma(zv, maskp[i], acc);
        }
        bp ^= 1;
    };

    // ---- Prologue: P(Z0-1),P(Z0),P(Z0+1) in P[0..2]; raw[0]=Z0+1, raw[1]=Z0+2 ----
    if (Z0 == 0) {
        loadp(0, rF[2], rM[2]);
        loadp(1, rF[0], rM[0]);
#pragma unroll
        for (int i = 0; i < RY; i++) { rF[1][i] = rF[2][i]; rM[1][i] = rM[2][i]; }
        stepP(1, 2, 0, 1);   // P(0) -> P[1]
#pragma unroll
        for (int i = 0; i < RY; i++) {   // P(-1) := P(0)
            pA[0][i] = pA[1][i]; pB[0][i] = pB[1][i]; pC[0][i] = pC[1][i];
        }
        loadp(2, rF[1], rM[1]);
        stepP(2, 0, 1, 2);   // P(1) -> P[2]
    } else {
        loadp(Z0 - 2, rF[0], rM[0]);
        loadp(Z0 - 1, rF[1], rM[1]);
        loadp(Z0,     rF[2], rM[2]);
        stepP(0, 1, 2, 0);   // P(Z0-1)
        loadp(Z0 + 1, rF[0], rM[0]);
        stepP(1, 2, 0, 1);   // P(Z0)
        loadp(Z0 + 2, rF[1], rM[1]);
        stepP(2, 0, 1, 2);   // P(Z0+1)
    }

    // ---- Main z sweep: 21 unrolled triples + 1 remainder (ZC = 64) ----
    auto body = [&](int j, int s0, int s1, int s2) {
        loadp(j + 3, rF[s2], rM[s2]);   // overwrite oldest raw slot (clamped)
        box2(s0, s1, s2);               // output plane j
        if (j != Z0 + ZC - 1) {
            if (j + 2 < NV) {
                stepP(s0, s1, s2, s0);  // P(j+2) -> oldest P slot
            } else {
#pragma unroll
                for (int i = 0; i < RY; i++) {  // P(j+2) := P(NV-1)
                    pA[s0][i] = pA[s2][i];
                    pB[s0][i] = pB[s2][i];
                    pC[s0][i] = pC[s2][i];
                }
            }
        }
    };
    for (int kb = 0; kb < ZC - 1; kb += 3) {
        body(Z0 + kb,     0, 1, 2);
        body(Z0 + kb + 1, 1, 2, 0);
        body(Z0 + kb + 2, 2, 0, 1);
    }
    body(Z0 + ZC - 1, 0, 1, 2);   // remainder (63 = 21*3 -> rotation is back to 0,1,2)

    // ---- Reduction ----
    float t = acc.x + acc.y;
#pragma unroll
    for (int o = 16; o > 0; o >>= 1)
        t += __shfl_xor_sync(FULL, t, o);
    if (tx == 0) wsum[ty] = t;
    __syncthreads();
    if (tx == 0 && ty == 0) {
        float s = 0.0f;
#pragma unroll
        for (int i = 0; i < BYT; i++) s += wsum[i];
        atomicAdd(&out[b], s * (-1.0f / (float)NV3));
    }
}

extern "C" void kernel_launch(void* const* d_in, const int* in_sizes, int n_in,
                              void* d_out, int out_size) {
    const float* F = (const float*)d_in[0];
    const float* M = (const float*)d_in[1];
    float* out = (float*)d_out;

    const int B = (int)(in_sizes[0] / (long long)NV3);

    zero_out_kernel<<<1, 32>>>(out, out_size);

    dim3 block(32, BYT, 1);
    dim3 grid(NV / TOUTX, NV / TOUTY, B * ZCHUNKS);
    lcc_kernel<<<grid, block>>>(F, M, out);
}

// round 14
// speedup vs baseline: 1.1266x; 1.0262x over previous
#include <cuda_runtime.h>

// LCC over [B=2,1,192,192,192] fp32, fully fused z-sweep.
// Round-14: R13 (92.6us: single-wave ZC=64, parity smem, 2 barriers/plane)
// + packed smem exchanges: (zf,zm) in one float4 array (STS.128/LDS.128),
// (zA,zB) in a float4 array + zD float2 -> ~40% fewer smem instructions
// per plane at identical registers/barriers/shuffles.

namespace {
constexpr int NV   = 192;
constexpr int NV2  = NV * NV;
constexpr long long NV3 = (long long)NV * NV2;
constexpr int BYT  = 8;
constexpr int RY   = 2;
constexpr int COVY = BYT * RY;      // 16 covered rows
constexpr int TOUTX = 48;           // outputs/block in x (lanes cover 64)
constexpr int TOUTY = COVY - 4;     // 12
constexpr int ZCHUNKS = 3;
constexpr int ZC   = NV / ZCHUNKS;  // 64 planes per CTA
constexpr float EPSV  = 1e-5f;
constexpr float INV27 = 1.0f / 27.0f;
constexpr unsigned FULL = 0xffffffffu;
}

__device__ __forceinline__ float2 a2(float2 a, float2 b) {
    float2 r;
    asm("{.reg .b64 ra,rb,rc;\n\t"
        "mov.b64 ra,{%2,%3};\n\t"
        "mov.b64 rb,{%4,%5};\n\t"
        "add.rn.f32x2 rc,ra,rb;\n\t"
        "mov.b64 {%0,%1},rc;}\n\t"
        : "=f"(r.x), "=f"(r.y)
        : "f"(a.x), "f"(a.y), "f"(b.x), "f"(b.y));
    return r;
}
__device__ __forceinline__ float2 m2(float2 a, float2 b) {
    float2 r;
    asm("{.reg .b64 ra,rb,rc;\n\t"
        "mov.b64 ra,{%2,%3};\n\t"
        "mov.b64 rb,{%4,%5};\n\t"
        "mul.rn.f32x2 rc,ra,rb;\n\t"
        "mov.b64 {%0,%1},rc;}\n\t"
        : "=f"(r.x), "=f"(r.y)
        : "f"(a.x), "f"(a.y), "f"(b.x), "f"(b.y));
    return r;
}
__device__ __forceinline__ float2 f2ma(float2 a, float2 b, float2 c) {
    float2 r;
    asm("{.reg .b64 ra,rb,rc,rd;\n\t"
        "mov.b64 ra,{%2,%3};\n\t"
        "mov.b64 rb,{%4,%5};\n\t"
        "mov.b64 rc,{%6,%7};\n\t"
        "fma.rn.f32x2 rd,ra,rb,rc;\n\t"
        "mov.b64 {%0,%1},rd;}\n\t"
        : "=f"(r.x), "=f"(r.y)
        : "f"(a.x), "f"(a.y), "f"(b.x), "f"(b.y), "f"(c.x), "f"(c.y));
    return r;
}

__global__ void zero_out_kernel(float* out, int n) {
    int i = blockIdx.x * blockDim.x + threadIdx.x;
    if (i < n) out[i] = 0.0f;
}

__global__ __launch_bounds__(256, 3)
void lcc_kernel(const float* __restrict__ gF,
                const float* __restrict__ gM,
                float* __restrict__ out)
{
    __shared__ float4 sZ  [2][COVY][33];   // (zf.x, zf.y, zm.x, zm.y)
    __shared__ float4 sQab[2][COVY][33];   // (zA.x, zA.y, zB.x, zB.y)
    __shared__ float2 sQd [2][COVY][33];   // zD
    __shared__ float  wsum[BYT];

    const int tx  = threadIdx.x;
    const int ty  = threadIdx.y;
    const int yl0 = ty * RY;
    const int b   = blockIdx.z / ZCHUNKS;
    const int Z0  = (blockIdx.z % ZCHUNKS) * ZC;

    const int x_nom0 = (int)blockIdx.x * TOUTX - 2 + 2 * tx;   // even
    const int xbase  = min(max(x_nom0, 0), NV - 2);
    const bool fixlo  = (x_nom0 < 0);
    const bool fixhi  = (x_nom0 > NV - 2);
    const bool fixXlo = (x_nom0 == 0);
    const bool fixXhi = (x_nom0 + 1 == NV - 1);

    const int y_nom0 = (int)blockIdx.y * TOUTY - 2 + yl0;
    const bool fixYup = (y_nom0 == 0);
    const bool fixYdn = (y_nom0 + 1 == NV - 1);

    int yoff[RY];
#pragma unroll
    for (int i = 0; i < RY; i++)
        yoff[i] = min(max(y_nom0 + i, 0), NV - 1) * NV + xbase;

    const float* F = gF + (long long)b * NV3;
    const float* M = gM + (long long)b * NV3;

    float2 rF[3][RY], rM[3][RY];               // raw plane ring
    float2 pA[3][RY], pB[3][RY], pC[3][RY];    // P plane ring (FM, FF, MM)
    float2 acc = make_float2(0.f, 0.f);
    int sp = 0, bp = 0;

    const float2 NEGI = make_float2(-INV27, -INV27);
    const float2 EPS2 = make_float2(EPSV, EPSV);

    const bool okl = (tx >= 1 && tx <= 24);
    float2 maskp[RY];
#pragma unroll
    for (int i = 0; i < RY; i++) {
        int yloc = yl0 + i;
        float m = (okl && yloc >= 2 && yloc < 2 + TOUTY) ? 1.0f : 0.0f;
        maskp[i] = make_float2(m, m);
    }

    auto loadp = [&](int z, float2 (&oF)[RY], float2 (&oM)[RY]) {
        z = min(max(z, 0), NV - 1);
        const float* fp = F + z * NV2;
        const float* mp = M + z * NV2;
#pragma unroll
        for (int i = 0; i < RY; i++) {
            float2 vF = __ldg(reinterpret_cast<const float2*>(fp + yoff[i]));
            float2 vM = __ldg(reinterpret_cast<const float2*>(mp + yoff[i]));
            oF[i].x = fixhi ? vF.y : vF.x;  oF[i].y = fixlo ? vF.x : vF.y;
            oM[i].x = fixhi ? vM.y : vM.x;  oM[i].y = fixlo ? vM.x : vM.y;
        }
    };

    const int rup = yl0 ? yl0 - 1 : 0;
    const int rdn = (yl0 + RY < COVY) ? yl0 + RY : COVY - 1;

    // P for the plane in raw slot ic (ip,ic,in_ = planes j-1, j, j+1); -> slot iw.
    auto stepP = [&](int ip, int ic, int in_, int iw) {
        float2 zf[RY], zm[RY];
#pragma unroll
        for (int i = 0; i < RY; i++) {
            zf[i] = a2(a2(rF[ip][i], rF[ic][i]), rF[in_][i]);
            zm[i] = a2(a2(rM[ip][i], rM[ic][i]), rM[in_][i]);
            sZ[sp][yl0 + i][tx] = make_float4(zf[i].x, zf[i].y, zm[i].x, zm[i].y);
        }
        __syncthreads();
        float4 up4 = sZ[sp][rup][tx], dn4 = sZ[sp][rdn][tx];
        float2 upF = make_float2(up4.x, up4.y), upM = make_float2(up4.z, up4.w);
        float2 dnF = make_float2(dn4.x, dn4.y), dnM = make_float2(dn4.z, dn4.w);
        float2 yf[RY], ym[RY];
        yf[0] = a2(a2(upF, zf[0]), zf[1]);  yf[1] = a2(a2(zf[0], zf[1]), dnF);
        ym[0] = a2(a2(upM, zm[0]), zm[1]);  ym[1] = a2(a2(zm[0], zm[1]), dnM);
#pragma unroll
        for (int i = 0; i < RY; i++) {
            float lF = __shfl_up_sync(FULL, yf[i].y, 1);
            float rG = __shfl_down_sync(FULL, yf[i].x, 1);
            float pF = yf[i].x + yf[i].y;
            float2 sF = make_float2(lF + pF, pF + rG);
            float lM = __shfl_up_sync(FULL, ym[i].y, 1);
            float rH = __shfl_down_sync(FULL, ym[i].x, 1);
            float pM = ym[i].x + ym[i].y;
            float2 sM = make_float2(lM + pM, pM + rH);
            float2 dF = f2ma(sF, NEGI, rF[ic][i]);
            float2 dM = f2ma(sM, NEGI, rM[ic][i]);
            pA[iw][i] = m2(dF, dM);
            pB[iw][i] = m2(dF, dF);
            pC[iw][i] = m2(dM, dM);
        }
        sp ^= 1;
    };

    // second box over P slots (i0,i1,i2) = P(j-1),P(j),P(j+1); score plane j.
    auto box2 = [&](int i0, int i1, int i2) {
        float2 zA[RY], zB[RY], zD[RY];
#pragma unroll
        for (int i = 0; i < RY; i++) {
            zA[i] = a2(a2(pA[i0][i], pA[i1][i]), pA[i2][i]);
            zB[i] = a2(a2(pB[i0][i], pB[i1][i]), pB[i2][i]);
            zD[i] = a2(a2(pC[i0][i], pC[i1][i]), pC[i2][i]);
            sQab[bp][yl0 + i][tx] = make_float4(zA[i].x, zA[i].y, zB[i].x, zB[i].y);
            sQd [bp][yl0 + i][tx] = zD[i];
        }
        __syncthreads();
        float4 uAB = sQab[bp][rup][tx], dAB = sQab[bp][rdn][tx];
        float2 uD  = sQd[bp][rup][tx],  dD  = sQd[bp][rdn][tx];
        float2 uA = make_float2(uAB.x, uAB.y), uB = make_float2(uAB.z, uAB.w);
        float2 dA = make_float2(dAB.x, dAB.y), dB = make_float2(dAB.z, dAB.w);
        uA = fixYup ? zA[0] : uA;  dA = fixYdn ? zA[1] : dA;
        uB = fixYup ? zB[0] : uB;  dB = fixYdn ? zB[1] : dB;
        uD = fixYup ? zD[0] : uD;  dD = fixYdn ? zD[1] : dD;
        float2 ybA[RY], ybB[RY], ybD[RY];
        ybA[0] = a2(a2(uA, zA[0]), zA[1]);  ybA[1] = a2(a2(zA[0], zA[1]), dA);
        ybB[0] = a2(a2(uB, zB[0]), zB[1]);  ybB[1] = a2(a2(zB[0], zB[1]), dB);
        ybD[0] = a2(a2(uD, zD[0]), zD[1]);  ybD[1] = a2(a2(zD[0], zD[1]), dD);
#pragma unroll
        for (int i = 0; i < RY; i++) {
            float lA = __shfl_up_sync(FULL, ybA[i].y, 1);
            float rA = __shfl_down_sync(FULL, ybA[i].x, 1);
            float pA_ = ybA[i].x + ybA[i].y;
            float2 crA = make_float2((fixXlo ? ybA[i].x : lA) + pA_,
                                     pA_ + (fixXhi ? ybA[i].y : rA));
            float lB = __shfl_up_sync(FULL, ybB[i].y, 1);
            float rB = __shfl_down_sync(FULL, ybB[i].x, 1);
            float pB_ = ybB[i].x + ybB[i].y;
            float2 crB = make_float2((fixXlo ? ybB[i].x : lB) + pB_,
                                     pB_ + (fixXhi ? ybB[i].y : rB));
            float lD = __shfl_up_sync(FULL, ybD[i].y, 1);
            float rD = __shfl_down_sync(FULL, ybD[i].x, 1);
            float pD_ = ybD[i].x + ybD[i].y;
            float2 crD = make_float2((fixXlo ? ybD[i].x : lD) + pD_,
                                     pD_ + (fixXhi ? ybD[i].y : rD));
            float2 num = m2(crA, crA);
            float2 den = f2ma(crB, crD, EPS2);
            float2 zv  = make_float2(__fdividef(num.x, den.x),
                                     __fdividef(num.y, den.y));
            acc = f2ma(zv, maskp[i], acc);
        }
        bp ^= 1;
    };

    // ---- Prologue: P(Z0-1),P(Z0),P(Z0+1) in P[0..2]; raw[0]=Z0+1, raw[1]=Z0+2 ----
    if (Z0 == 0) {
        loadp(0, rF[2], rM[2]);
        loadp(1, rF[0], rM[0]);
#pragma unroll
        for (int i = 0; i < RY; i++) { rF[1][i] = rF[2][i]; rM[1][i] = rM[2][i]; }
        stepP(1, 2, 0, 1);   // P(0) -> P[1]
#pragma unroll
        for (int i = 0; i < RY; i++) {   // P(-1) := P(0)
            pA[0][i] = pA[1][i]; pB[0][i] = pB[1][i]; pC[0][i] = pC[1][i];
        }
        loadp(2, rF[1], rM[1]);
        stepP(2, 0, 1, 2);   // P(1) -> P[2]
    } else {
        loadp(Z0 - 2, rF[0], rM[0]);
        loadp(Z0 - 1, rF[1], rM[1]);
        loadp(Z0,     rF[2], rM[2]);
        stepP(0, 1, 2, 0);   // P(Z0-1)
        loadp(Z0 + 1, rF[0], rM[0]);
        stepP(1, 2, 0, 1);   // P(Z0)
        loadp(Z0 + 2, rF[1], rM[1]);
        stepP(2, 0, 1, 2);   // P(Z0+1)
    }

    // ---- Main z sweep: 21 unrolled triples + 1 remainder (ZC = 64) ----
    auto body = [&](int j, int s0, int s1, int s2) {
        loadp(j + 3, rF[s2], rM[s2]);   // overwrite oldest raw slot (clamped)
        box2(s0, s1, s2);               // output plane j
        if (j != Z0 + ZC - 1) {
            if (j + 2 < NV) {
                stepP(s0, s1, s2, s0);  // P(j+2) -> oldest P slot
            } else {
#pragma unroll
                for (int i = 0; i < RY; i++) {  // P(j+2) := P(NV-1)
                    pA[s0][i] = pA[s2][i];
                    pB[s0][i] = pB[s2][i];
                    pC[s0][i] = pC[s2][i];
                }
            }
        }
    };
    for (int kb = 0; kb < ZC - 1; kb += 3) {
        body(Z0 + kb,     0, 1, 2);
        body(Z0 + kb + 1, 1, 2, 0);
        body(Z0 + kb + 2, 2, 0, 1);
    }
    body(Z0 + ZC - 1, 0, 1, 2);   // remainder (63 = 21*3 -> rotation back to 0,1,2)

    // ---- Reduction ----
    float t = acc.x + acc.y;
#pragma unroll
    for (int o = 16; o > 0; o >>= 1)
        t += __shfl_xor_sync(FULL, t, o);
    if (tx == 0) wsum[ty] = t;
    __syncthreads();
    if (tx == 0 && ty == 0) {
        float s = 0.0f;
#pragma unroll
        for (int i = 0; i < BYT; i++) s += wsum[i];
        atomicAdd(&out[b], s * (-1.0f / (float)NV3));
    }
}

extern "C" void kernel_launch(void* const* d_in, const int* in_sizes, int n_in,
                              void* d_out, int out_size) {
    const float* F = (const float*)d_in[0];
    const float* M = (const float*)d_in[1];
    float* out = (float*)d_out;

    const int B = (int)(in_sizes[0] / (long long)NV3);

    zero_out_kernel<<<1, 32>>>(out, out_size);

    dim3 block(32, BYT, 1);
    dim3 grid(NV / TOUTX, NV / TOUTY, B * ZCHUNKS);
    lcc_kernel<<<grid, block>>>(F, M, out);
}